// round 16
// baseline (speedup 1.0000x reference)
#include <cuda_runtime.h>
#include <cuda_fp16.h>
#include <cstdint>
#include <cstddef>

#define BTILE  14
#define NB     16           // padded batch dim (2 n8 tiles)
#define S_LEN  256
#define F_IN   5
#define HID    64
#define NTH    256

#define KP0    88           // B0 row len (fp16): 80 used
#define KP1    152          // B1 row len (fp16): 128 used
#define KT0    5
#define KT1    8

// SMEM byte offsets (per CTA 84,480 B -> 2 CTAs/SM)
#define SM_AF1 0                               // layer1 A-fragments: 8w*8kt*2mt*512 = 65536
#define SM_B0A 65536                           // B0 ping: 16*88*2 = 2816
#define SM_B0B (SM_B0A + NB * KP0 * 2)         // B0 pong
#define SM_B1A (SM_B0B + NB * KP0 * 2)         // B1 ping: 16*152*2 = 4864
#define SM_B1B (SM_B1A + NB * KP1 * 2)         // B1 pong
#define SM_HBF (SM_B1B + NB * KP1 * 2)         // 14*64*4 = 3584
#define SM_TOT (SM_HBF + BTILE * HID * 4)      // 84480

__device__ __forceinline__ uint32_t smem_u32(const void* p) {
    uint32_t a;
    asm("{ .reg .u64 t; cvta.to.shared.u64 t, %1; cvt.u32.u64 %0, t; }" : "=r"(a) : "l"(p));
    return a;
}
__device__ __forceinline__ uint32_t lds32(uint32_t a) {
    uint32_t v;
    asm volatile("ld.shared.b32 %0, [%1];" : "=r"(v) : "r"(a));
    return v;
}
__device__ __forceinline__ void lds128(uint32_t a, uint32_t* r) {
    asm volatile("ld.shared.v4.b32 {%0,%1,%2,%3}, [%4];"
                 : "=r"(r[0]), "=r"(r[1]), "=r"(r[2]), "=r"(r[3]) : "r"(a));
}

// m16n8k16 row.col f32 += f16*f16 (plain sm_80+ PTX)
__device__ __forceinline__ void mma16816(float* c, const uint32_t* a, const uint32_t* b) {
    asm volatile(
        "mma.sync.aligned.m16n8k16.row.col.f32.f16.f16.f32 "
        "{%0,%1,%2,%3}, {%4,%5,%6,%7}, {%8,%9}, {%0,%1,%2,%3};"
        : "+f"(c[0]), "+f"(c[1]), "+f"(c[2]), "+f"(c[3])
        : "r"(a[0]), "r"(a[1]), "r"(a[2]), "r"(a[3]), "r"(b[0]), "r"(b[1]));
}

// ---------- activations ----------
__device__ __forceinline__ float tanhap(float x) {
    float y;
    asm("tanh.approx.f32 %0, %1;" : "=f"(y) : "f"(x));
    return y;
}
__device__ __forceinline__ float sigm(float x) {
    return fmaf(tanhap(0.5f * x), 0.5f, 0.5f);
}
__device__ __forceinline__ uint32_t packh2(float a, float b) {
    __half2 h = __floats2half2_rn(a, b);
    return *(uint32_t*)&h;
}

__device__ __forceinline__ float mlp_head(const float* __restrict__ hb,
                                          const float* __restrict__ w1,
                                          const float* __restrict__ b1,
                                          const float* __restrict__ w2,
                                          const float* __restrict__ b2) {
    float acc = b2[0];
    #pragma unroll 4
    for (int u = 0; u < 16; u++) {
        float s = b1[u];
        #pragma unroll 8
        for (int k = 0; k < HID; k++) s += hb[k] * w1[u * HID + k];
        acc += fmaxf(s, 0.0f) * w2[u];
    }
    return sigm(acc);
}

__global__ void __launch_bounds__(NTH, 2)
lstm_behavior_kernel(const float* __restrict__ x,
                     const float* __restrict__ w_ih0, const float* __restrict__ w_hh0,
                     const float* __restrict__ b_ih0, const float* __restrict__ b_hh0,
                     const float* __restrict__ w_ih1, const float* __restrict__ w_hh1,
                     const float* __restrict__ b_ih1, const float* __restrict__ b_hh1,
                     const float* __restrict__ eng_w1, const float* __restrict__ eng_b1,
                     const float* __restrict__ eng_w2, const float* __restrict__ eng_b2,
                     const float* __restrict__ prop_w1, const float* __restrict__ prop_b1,
                     const float* __restrict__ prop_w2, const float* __restrict__ prop_b2,
                     const float* __restrict__ seg_w, const float* __restrict__ seg_b,
                     float* __restrict__ out, int Btot) {
    extern __shared__ char smem[];
    const uint32_t sb = smem_u32(smem);
    const int tid  = threadIdx.x;
    const int w    = tid >> 5, lane = tid & 31;
    const int gid  = lane >> 2, tg = lane & 3;
    const int c    = w * 8 + gid;       // my cell (output permutation)

    // ---- zero B tiles (both parities; padding must be 0) ----
    for (int i = tid; i < (SM_HBF - SM_B0A) / 4; i += NTH)
        ((uint32_t*)(smem + SM_B0A))[i] = 0;

    // ---- fill AF1: layer1 A-fragments, PERMUTED rows ----
    // MMA row (ww*32 + mtt*16 + (q&1)*8 + g8) <- gate m=2*mtt+(q&1) of cell ww*8+g8
    for (int fid = tid; fid < 8 * KT1 * 2 * 32 * 4; fid += NTH) {
        int q   = fid & 3;
        int ln  = (fid >> 2) & 31;
        int mtt = (fid >> 7) & 1;
        int ktt = (fid >> 8) & 7;
        int ww  = fid >> 11;
        int g8 = ln >> 2, tt = ln & 3;
        int row = (2 * mtt + (q & 1)) * 64 + ww * 8 + g8;      // PyTorch gate row
        int kk  = ktt * 16 + 2 * tt + (q >> 1) * 8;
        float v0 = (kk < 64)     ? w_ih1[row * HID + kk]     : w_hh1[row * HID + kk - 64];
        float v1 = (kk + 1 < 64) ? w_ih1[row * HID + kk + 1] : w_hh1[row * HID + kk + 1 - 64];
        *(uint32_t*)(smem + SM_AF1 + (fid >> 2) * 16 + q * 4) = packh2(v0, v1);
    }

    // ---- hoist layer0 A-fragments (permuted rows) straight from gmem ----
    uint32_t aL0[KT0][2][4];
    #pragma unroll
    for (int kt = 0; kt < KT0; kt++)
        #pragma unroll
        for (int mt = 0; mt < 2; mt++)
            #pragma unroll
            for (int q = 0; q < 4; q++) {
                int row = (2 * mt + (q & 1)) * 64 + c;          // PyTorch gate row
                int kk  = kt * 16 + 2 * tg + (q >> 1) * 8;
                float v0 = (kk < 64) ? w_hh0[row * HID + kk]
                         : (kk < 64 + F_IN) ? w_ih0[row * F_IN + kk - 64] : 0.0f;
                int k1 = kk + 1;
                float v1 = (k1 < 64) ? w_hh0[row * HID + k1]
                         : (k1 < 64 + F_IN) ? w_ih0[row * F_IN + k1 - 64] : 0.0f;
                aL0[kt][mt][q] = packh2(v0, v1);
            }

    // ---- per-cell biases (i,f,g,o) ----
    float bz0[4], bz1[4];
    #pragma unroll
    for (int m = 0; m < 4; m++) {
        bz0[m] = b_ih0[m * HID + c] + b_hh0[m * HID + c];
        bz1[m] = b_ih1[m * HID + c] + b_hh1[m * HID + c];
    }
    float cA[4], cB[4];     // c-state: idx nt*2+p, batch b = nt*8+2tg+p
    #pragma unroll
    for (int j = 0; j < 4; j++) { cA[j] = 0.0f; cB[j] = 0.0f; }

    __syncthreads();   // B tiles zeroed before x staging writes B0A

    // ---- x staging ----
    const float* xptr = nullptr;
    float xreg = 0.0f;
    int xrel = 0;
    if (tid < BTILE * F_IN) {          // tid < 70
        int xb = tid / F_IN, xf = tid - xb * F_IN;
        int gxb = blockIdx.x * BTILE + xb;
        if (gxb > Btot - 1) gxb = Btot - 1;
        xptr = x + (size_t)gxb * (S_LEN * F_IN) + xf;
        xrel = (xb * KP0 + 64 + xf) * 2;
        *(__half*)(smem + SM_B0A + xrel) = __float2half_rn(xptr[0]);   // x(0) -> ping
        xreg = xptr[F_IN];
    }
    float* HBF = (float*)(smem + SM_HBF);
    const uint32_t af1w = sb + SM_AF1 + (uint32_t)w * 8192 + lane * 16;
    __syncthreads();

    float C[2][2][4];
    const int b2tg = 2 * tg;

    for (int t = 0; t < S_LEN; ++t) {
        const int b0rd = (t & 1) ? SM_B0B : SM_B0A;     // hA(t-1), x(t)
        const int b0wr = (t & 1) ? SM_B0A : SM_B0B;     // hA(t), x(t+1)
        const int b1rd = (t & 1) ? SM_B1B : SM_B1A;     // P3(t) source: hA(t) + hB(t-1)
        const int b1wr = (t & 1) ? SM_B1A : SM_B1B;     // P4(t) dest: hB(t)

        // ===== P1: L0 gemm (reads B0[rd]) =====
        #pragma unroll
        for (int a = 0; a < 2; a++)
            #pragma unroll
            for (int b = 0; b < 2; b++)
                #pragma unroll
                for (int e = 0; e < 4; e++) C[a][b][e] = 0.0f;
        #pragma unroll
        for (int kt = 0; kt < KT0; kt++) {
            uint32_t B[2][2];
            #pragma unroll
            for (int nt = 0; nt < 2; nt++) {
                uint32_t ba = sb + b0rd + (uint32_t)((nt * 8 + gid) * KP0 + kt * 16 + b2tg) * 2;
                B[nt][0] = lds32(ba);
                B[nt][1] = lds32(ba + 16);
            }
            #pragma unroll
            for (int mt = 0; mt < 2; mt++)
                #pragma unroll
                for (int nt = 0; nt < 2; nt++)
                    mma16816(C[mt][nt], aL0[kt][mt], B[nt]);
        }

        // ===== P2: L0 update in registers; hA(t)->B0[wr]+B1[rd]; x(t+1)->B0[wr] =====
        #pragma unroll
        for (int nt = 0; nt < 2; nt++)
            #pragma unroll
            for (int p = 0; p < 2; p++) {
                int j = nt * 2 + p;
                int b = nt * 8 + b2tg + p;
                float gi = C[0][nt][p]     + bz0[0];
                float gf = C[0][nt][2 + p] + bz0[1];
                float gg = C[1][nt][p]     + bz0[2];
                float go = C[1][nt][2 + p] + bz0[3];
                float cn = sigm(gf) * cA[j] + sigm(gi) * tanhap(gg);
                cA[j] = cn;
                __half hh = __float2half_rn(sigm(go) * tanhap(cn));
                *(__half*)(smem + b0wr + (b * KP0 + c) * 2) = hh;
                *(__half*)(smem + b1rd + (b * KP1 + c) * 2) = hh;
            }
        if (tid < BTILE * F_IN) {
            *(__half*)(smem + b0wr + xrel) = __float2half_rn(xreg);
            int tn = (t + 2 < S_LEN) ? (t + 2) : (S_LEN - 1);
            xreg = xptr[tn * F_IN];
        }
        __syncthreads();                 // THE step barrier: hA(t)+hB(t-1) visible in B1[rd]

        // ===== P3: L1 gemm (reads B1[rd]) =====
        #pragma unroll
        for (int a = 0; a < 2; a++)
            #pragma unroll
            for (int b = 0; b < 2; b++)
                #pragma unroll
                for (int e = 0; e < 4; e++) C[a][b][e] = 0.0f;
        #pragma unroll
        for (int kt = 0; kt < KT1; kt++) {
            uint32_t B[2][2];
            #pragma unroll
            for (int nt = 0; nt < 2; nt++) {
                uint32_t ba = sb + b1rd + (uint32_t)((nt * 8 + gid) * KP1 + kt * 16 + b2tg) * 2;
                B[nt][0] = lds32(ba);
                B[nt][1] = lds32(ba + 16);
            }
            #pragma unroll
            for (int mt = 0; mt < 2; mt++) {
                uint32_t A[4];
                lds128(af1w + (uint32_t)(kt * 2 + mt) * 512, A);
                #pragma unroll
                for (int nt = 0; nt < 2; nt++)
                    mma16816(C[mt][nt], A, B[nt]);
            }
        }

        // ===== P4: L1 update in registers; hB(t) -> B1[wr] cols 64-127 (no barrier) =====
        #pragma unroll
        for (int nt = 0; nt < 2; nt++)
            #pragma unroll
            for (int p = 0; p < 2; p++) {
                int j = nt * 2 + p;
                int b = nt * 8 + b2tg + p;
                float gi = C[0][nt][p]     + bz1[0];
                float gf = C[0][nt][2 + p] + bz1[1];
                float gg = C[1][nt][p]     + bz1[2];
                float go = C[1][nt][2 + p] + bz1[3];
                float cn = sigm(gf) * cB[j] + sigm(gi) * tanhap(gg);
                cB[j] = cn;
                float h = sigm(go) * tanhap(cn);
                *(__half*)(smem + b1wr + (b * KP1 + 64 + c) * 2) = __float2half_rn(h);
                if (t == S_LEN - 1 && b < BTILE) HBF[b * HID + c] = h;
            }
        // hB(t) visibility for P3(t+1): covered by P2(t+1)'s __syncthreads()
    }
    __syncthreads();

    // ---- heads ----
    if (tid < BTILE) {
        int b = blockIdx.x * BTILE + tid;
        if (b < Btot) {
            const float* hb = HBF + tid * HID;
            out[b]        = mlp_head(hb, eng_w1, eng_b1, eng_w2, eng_b2);
            out[Btot + b] = mlp_head(hb, prop_w1, prop_b1, prop_w2, prop_b2);
            #pragma unroll
            for (int j = 0; j < 5; j++) {
                float s = seg_b[j];
                #pragma unroll 8
                for (int k = 0; k < HID; k++) s += hb[k] * seg_w[j * HID + k];
                out[2 * Btot + b * 5 + j] = s;
            }
        }
    }
}

extern "C" void kernel_launch(void* const* d_in, const int* in_sizes, int n_in,
                              void* d_out, int out_size) {
    const float* x       = (const float*)d_in[0];
    const float* w_ih0   = (const float*)d_in[1];
    const float* w_hh0   = (const float*)d_in[2];
    const float* b_ih0   = (const float*)d_in[3];
    const float* b_hh0   = (const float*)d_in[4];
    const float* w_ih1   = (const float*)d_in[5];
    const float* w_hh1   = (const float*)d_in[6];
    const float* b_ih1   = (const float*)d_in[7];
    const float* b_hh1   = (const float*)d_in[8];
    const float* eng_w1  = (const float*)d_in[9];
    const float* eng_b1  = (const float*)d_in[10];
    const float* eng_w2  = (const float*)d_in[11];
    const float* eng_b2  = (const float*)d_in[12];
    const float* prop_w1 = (const float*)d_in[13];
    const float* prop_b1 = (const float*)d_in[14];
    const float* prop_w2 = (const float*)d_in[15];
    const float* prop_b2 = (const float*)d_in[16];
    const float* seg_w   = (const float*)d_in[17];
    const float* seg_b   = (const float*)d_in[18];
    float* out = (float*)d_out;

    int Btot = in_sizes[0] / (S_LEN * F_IN);        // 4096
    int grid = (Btot + BTILE - 1) / BTILE;          // 293

    cudaFuncSetAttribute(lstm_behavior_kernel,
                         cudaFuncAttributeMaxDynamicSharedMemorySize, SM_TOT);

    lstm_behavior_kernel<<<grid, NTH, SM_TOT>>>(
        x, w_ih0, w_hh0, b_ih0, b_hh0, w_ih1, w_hh1, b_ih1, b_hh1,
        eng_w1, eng_b1, eng_w2, eng_b2, prop_w1, prop_b1, prop_w2, prop_b2,
        seg_w, seg_b, out, Btot);
}

// round 17
// speedup vs baseline: 1.0157x; 1.0157x over previous
#include <cuda_runtime.h>
#include <cuda_fp16.h>
#include <cstdint>
#include <cstddef>

#define BTILE  14
#define NB     16           // padded batch dim (2 n8 tiles)
#define S_LEN  256
#define F_IN   5
#define HID    64
#define NTH    256

#define KP0    88           // B0 row len (fp16): 80 used
#define KP1    152          // B1 row len (fp16): 128 used
#define KT0    5
#define KT1    8

// SMEM byte offsets (per CTA 84,480 B -> 2 CTAs/SM)
#define SM_AF1 0                               // layer1 A-fragments: 8w*8kt*2mt*512 = 65536
#define SM_B0A 65536                           // B0 ping: 16*88*2 = 2816
#define SM_B0B (SM_B0A + NB * KP0 * 2)         // B0 pong
#define SM_B1A (SM_B0B + NB * KP0 * 2)         // B1 ping: 16*152*2 = 4864
#define SM_B1B (SM_B1A + NB * KP1 * 2)         // B1 pong
#define SM_HBF (SM_B1B + NB * KP1 * 2)         // 14*64*4 = 3584
#define SM_TOT (SM_HBF + BTILE * HID * 4)      // 84480

__device__ __forceinline__ uint32_t smem_u32(const void* p) {
    uint32_t a;
    asm("{ .reg .u64 t; cvta.to.shared.u64 t, %1; cvt.u32.u64 %0, t; }" : "=r"(a) : "l"(p));
    return a;
}
__device__ __forceinline__ uint32_t lds32(uint32_t a) {
    uint32_t v;
    asm volatile("ld.shared.b32 %0, [%1];" : "=r"(v) : "r"(a));
    return v;
}
__device__ __forceinline__ void lds128(uint32_t a, uint32_t* r) {
    asm volatile("ld.shared.v4.b32 {%0,%1,%2,%3}, [%4];"
                 : "=r"(r[0]), "=r"(r[1]), "=r"(r[2]), "=r"(r[3]) : "r"(a));
}

// m16n8k16 row.col f32 += f16*f16 (plain sm_80+ PTX)
__device__ __forceinline__ void mma16816(float* c, const uint32_t* a, const uint32_t* b) {
    asm volatile(
        "mma.sync.aligned.m16n8k16.row.col.f32.f16.f16.f32 "
        "{%0,%1,%2,%3}, {%4,%5,%6,%7}, {%8,%9}, {%0,%1,%2,%3};"
        : "+f"(c[0]), "+f"(c[1]), "+f"(c[2]), "+f"(c[3])
        : "r"(a[0]), "r"(a[1]), "r"(a[2]), "r"(a[3]), "r"(b[0]), "r"(b[1]));
}

// ---------- activations ----------
__device__ __forceinline__ float tanhap(float x) {
    float y;
    asm("tanh.approx.f32 %0, %1;" : "=f"(y) : "f"(x));
    return y;
}
__device__ __forceinline__ float sigm(float x) {
    return fmaf(tanhap(0.5f * x), 0.5f, 0.5f);
}
__device__ __forceinline__ uint32_t packh2(float a, float b) {
    __half2 h = __floats2half2_rn(a, b);
    return *(uint32_t*)&h;
}

__device__ __forceinline__ float mlp_head(const float* __restrict__ hb,
                                          const float* __restrict__ w1,
                                          const float* __restrict__ b1,
                                          const float* __restrict__ w2,
                                          const float* __restrict__ b2) {
    float acc = b2[0];
    #pragma unroll 4
    for (int u = 0; u < 16; u++) {
        float s = b1[u];
        #pragma unroll 8
        for (int k = 0; k < HID; k++) s += hb[k] * w1[u * HID + k];
        acc += fmaxf(s, 0.0f) * w2[u];
    }
    return sigm(acc);
}

__global__ void __launch_bounds__(NTH, 2)
lstm_behavior_kernel(const float* __restrict__ x,
                     const float* __restrict__ w_ih0, const float* __restrict__ w_hh0,
                     const float* __restrict__ b_ih0, const float* __restrict__ b_hh0,
                     const float* __restrict__ w_ih1, const float* __restrict__ w_hh1,
                     const float* __restrict__ b_ih1, const float* __restrict__ b_hh1,
                     const float* __restrict__ eng_w1, const float* __restrict__ eng_b1,
                     const float* __restrict__ eng_w2, const float* __restrict__ eng_b2,
                     const float* __restrict__ prop_w1, const float* __restrict__ prop_b1,
                     const float* __restrict__ prop_w2, const float* __restrict__ prop_b2,
                     const float* __restrict__ seg_w, const float* __restrict__ seg_b,
                     float* __restrict__ out, int Btot) {
    extern __shared__ char smem[];
    const uint32_t sb = smem_u32(smem);
    const int tid  = threadIdx.x;
    const int w    = tid >> 5, lane = tid & 31;
    const int gid  = lane >> 2, tg = lane & 3;
    const int c    = w * 8 + gid;       // my cell (output permutation)

    // ---- zero B tiles (both parities; padding must stay 0) ----
    for (int i = tid; i < (SM_HBF - SM_B0A) / 4; i += NTH)
        ((uint32_t*)(smem + SM_B0A))[i] = 0;

    // ---- fill AF1: layer1 A-fragments, PERMUTED rows ----
    for (int fid = tid; fid < 8 * KT1 * 2 * 32 * 4; fid += NTH) {
        int q   = fid & 3;
        int ln  = (fid >> 2) & 31;
        int mtt = (fid >> 7) & 1;
        int ktt = (fid >> 8) & 7;
        int ww  = fid >> 11;
        int g8 = ln >> 2, tt = ln & 3;
        int row = (2 * mtt + (q & 1)) * 64 + ww * 8 + g8;      // PyTorch gate row
        int kk  = ktt * 16 + 2 * tt + (q >> 1) * 8;
        float v0 = (kk < 64)     ? w_ih1[row * HID + kk]     : w_hh1[row * HID + kk - 64];
        float v1 = (kk + 1 < 64) ? w_ih1[row * HID + kk + 1] : w_hh1[row * HID + kk + 1 - 64];
        *(uint32_t*)(smem + SM_AF1 + (fid >> 2) * 16 + q * 4) = packh2(v0, v1);
    }

    // ---- hoist layer0 A-fragments (permuted rows) straight from gmem ----
    uint32_t aL0[KT0][2][4];
    #pragma unroll
    for (int kt = 0; kt < KT0; kt++)
        #pragma unroll
        for (int mt = 0; mt < 2; mt++)
            #pragma unroll
            for (int q = 0; q < 4; q++) {
                int row = (2 * mt + (q & 1)) * 64 + c;          // PyTorch gate row
                int kk  = kt * 16 + 2 * tg + (q >> 1) * 8;
                float v0 = (kk < 64) ? w_hh0[row * HID + kk]
                         : (kk < 64 + F_IN) ? w_ih0[row * F_IN + kk - 64] : 0.0f;
                int k1 = kk + 1;
                float v1 = (k1 < 64) ? w_hh0[row * HID + k1]
                         : (k1 < 64 + F_IN) ? w_ih0[row * F_IN + k1 - 64] : 0.0f;
                aL0[kt][mt][q] = packh2(v0, v1);
            }

    // ---- per-cell biases (i,f,g,o) ----
    float bz0[4], bz1[4];
    #pragma unroll
    for (int m = 0; m < 4; m++) {
        bz0[m] = b_ih0[m * HID + c] + b_hh0[m * HID + c];
        bz1[m] = b_ih1[m * HID + c] + b_hh1[m * HID + c];
    }
    float cA[4], cB[4];     // c-state: idx nt*2+p, batch b = nt*8+2tg+p
    #pragma unroll
    for (int j = 0; j < 4; j++) { cA[j] = 0.0f; cB[j] = 0.0f; }

    __syncthreads();   // tiles zeroed before x(0) staging

    // ---- x staging ----
    const float* xptr = nullptr;
    float xreg = 0.0f;
    int xrel = 0;
    if (tid < BTILE * F_IN) {          // tid < 70
        int xb = tid / F_IN, xf = tid - xb * F_IN;
        int gxb = blockIdx.x * BTILE + xb;
        if (gxb > Btot - 1) gxb = Btot - 1;
        xptr = x + (size_t)gxb * (S_LEN * F_IN) + xf;
        xrel = (xb * KP0 + 64 + xf) * 2;
        *(__half*)(smem + SM_B0A + xrel) = __float2half_rn(xptr[0]);   // x(0) -> B0A
        xreg = xptr[F_IN];                                             // prefetch x(1)
    }
    float* HBF = (float*)(smem + SM_HBF);
    const uint32_t af1w = sb + SM_AF1 + (uint32_t)w * 8192 + lane * 16;
    __syncthreads();   // x(0) + AF1 visible

    float C[2][2][4];
    const int b2tg = 2 * tg;

    // ================= prologue: L0 step 0 =================
    {
        #pragma unroll
        for (int a = 0; a < 2; a++)
            #pragma unroll
            for (int b = 0; b < 2; b++)
                #pragma unroll
                for (int e = 0; e < 4; e++) C[a][b][e] = 0.0f;
        #pragma unroll
        for (int kt = 0; kt < KT0; kt++) {
            uint32_t B[2][2];
            #pragma unroll
            for (int nt = 0; nt < 2; nt++) {
                uint32_t ba = sb + SM_B0A + (uint32_t)((nt * 8 + gid) * KP0 + kt * 16 + b2tg) * 2;
                B[nt][0] = lds32(ba);
                B[nt][1] = lds32(ba + 16);
            }
            #pragma unroll
            for (int mt = 0; mt < 2; mt++)
                #pragma unroll
                for (int nt = 0; nt < 2; nt++)
                    mma16816(C[mt][nt], aL0[kt][mt], B[nt]);
        }
        // update0: hA(0) -> B0B cols0-63 + B1A cols0-63; x(1) -> B0B
        #pragma unroll
        for (int nt = 0; nt < 2; nt++)
            #pragma unroll
            for (int p = 0; p < 2; p++) {
                int j = nt * 2 + p;
                int b = nt * 8 + b2tg + p;
                float gi = C[0][nt][p]     + bz0[0];
                float gf = C[0][nt][2 + p] + bz0[1];
                float gg = C[1][nt][p]     + bz0[2];
                float go = C[1][nt][2 + p] + bz0[3];
                float cn = sigm(gf) * cA[j] + sigm(gi) * tanhap(gg);
                cA[j] = cn;
                __half hh = __float2half_rn(sigm(go) * tanhap(cn));
                *(__half*)(smem + SM_B0B + (b * KP0 + c) * 2) = hh;
                *(__half*)(smem + SM_B1A + (b * KP1 + c) * 2) = hh;
            }
        if (tid < BTILE * F_IN) {
            *(__half*)(smem + SM_B0B + xrel) = __float2half_rn(xreg);
            xreg = xptr[2 * F_IN];
        }
    }

    // ================= main loop: iteration t = L1(t) + L0(t+1) =================
    for (int t = 0; t < S_LEN; ++t) {
        const int b1rd = (t & 1) ? SM_B1B : SM_B1A;   // hA(t) | hB(t-1)
        const int b1wr = (t & 1) ? SM_B1A : SM_B1B;   // <- hB(t), hA(t+1)
        const int b0rd = (t & 1) ? SM_B0A : SM_B0B;   // hA(t) | x(t+1)
        const int b0wr = (t & 1) ? SM_B0B : SM_B0A;   // <- hA(t+1), x(t+2)

        __syncthreads();   // THE step barrier: all t-1 writes visible

        // ===== gemm L1(t): reads b1rd =====
        #pragma unroll
        for (int a = 0; a < 2; a++)
            #pragma unroll
            for (int b = 0; b < 2; b++)
                #pragma unroll
                for (int e = 0; e < 4; e++) C[a][b][e] = 0.0f;
        #pragma unroll
        for (int kt = 0; kt < KT1; kt++) {
            uint32_t B[2][2];
            #pragma unroll
            for (int nt = 0; nt < 2; nt++) {
                uint32_t ba = sb + b1rd + (uint32_t)((nt * 8 + gid) * KP1 + kt * 16 + b2tg) * 2;
                B[nt][0] = lds32(ba);
                B[nt][1] = lds32(ba + 16);
            }
            #pragma unroll
            for (int mt = 0; mt < 2; mt++) {
                uint32_t A[4];
                lds128(af1w + (uint32_t)(kt * 2 + mt) * 512, A);
                #pragma unroll
                for (int nt = 0; nt < 2; nt++)
                    mma16816(C[mt][nt], A, B[nt]);
            }
        }

        // ===== update1(t): hB(t) -> b1wr cols 64-127 (frees C per-nt) =====
        #pragma unroll
        for (int nt = 0; nt < 2; nt++)
            #pragma unroll
            for (int p = 0; p < 2; p++) {
                int j = nt * 2 + p;
                int b = nt * 8 + b2tg + p;
                float gi = C[0][nt][p]     + bz1[0];
                float gf = C[0][nt][2 + p] + bz1[1];
                float gg = C[1][nt][p]     + bz1[2];
                float go = C[1][nt][2 + p] + bz1[3];
                float cn = sigm(gf) * cB[j] + sigm(gi) * tanhap(gg);
                cB[j] = cn;
                float h = sigm(go) * tanhap(cn);
                *(__half*)(smem + b1wr + (b * KP1 + 64 + c) * 2) = __float2half_rn(h);
                if (t == S_LEN - 1 && b < BTILE) HBF[b * HID + c] = h;
            }

        // ===== gemm L0(t+1): reads b0rd (hA(t), x(t+1)) — overlaps update1 =====
        #pragma unroll
        for (int a = 0; a < 2; a++)
            #pragma unroll
            for (int b = 0; b < 2; b++)
                #pragma unroll
                for (int e = 0; e < 4; e++) C[a][b][e] = 0.0f;
        #pragma unroll
        for (int kt = 0; kt < KT0; kt++) {
            uint32_t B[2][2];
            #pragma unroll
            for (int nt = 0; nt < 2; nt++) {
                uint32_t ba = sb + b0rd + (uint32_t)((nt * 8 + gid) * KP0 + kt * 16 + b2tg) * 2;
                B[nt][0] = lds32(ba);
                B[nt][1] = lds32(ba + 16);
            }
            #pragma unroll
            for (int mt = 0; mt < 2; mt++)
                #pragma unroll
                for (int nt = 0; nt < 2; nt++)
                    mma16816(C[mt][nt], aL0[kt][mt], B[nt]);
        }

        // ===== update0(t+1): hA(t+1) -> b0wr + b1wr cols 0-63; x(t+2) -> b0wr =====
        #pragma unroll
        for (int nt = 0; nt < 2; nt++)
            #pragma unroll
            for (int p = 0; p < 2; p++) {
                int j = nt * 2 + p;
                int b = nt * 8 + b2tg + p;
                float gi = C[0][nt][p]     + bz0[0];
                float gf = C[0][nt][2 + p] + bz0[1];
                float gg = C[1][nt][p]     + bz0[2];
                float go = C[1][nt][2 + p] + bz0[3];
                float cn = sigm(gf) * cA[j] + sigm(gi) * tanhap(gg);
                cA[j] = cn;
                __half hh = __float2half_rn(sigm(go) * tanhap(cn));
                *(__half*)(smem + b0wr + (b * KP0 + c) * 2) = hh;
                *(__half*)(smem + b1wr + (b * KP1 + c) * 2) = hh;
            }
        if (tid < BTILE * F_IN) {
            *(__half*)(smem + b0wr + xrel) = __float2half_rn(xreg);
            int tn = (t + 3 < S_LEN) ? (t + 3) : (S_LEN - 1);
            xreg = xptr[tn * F_IN];
        }
    }
    __syncthreads();

    // ---- heads ----
    if (tid < BTILE) {
        int b = blockIdx.x * BTILE + tid;
        if (b < Btot) {
            const float* hb = HBF + tid * HID;
            out[b]        = mlp_head(hb, eng_w1, eng_b1, eng_w2, eng_b2);
            out[Btot + b] = mlp_head(hb, prop_w1, prop_b1, prop_w2, prop_b2);
            #pragma unroll
            for (int j = 0; j < 5; j++) {
                float s = seg_b[j];
                #pragma unroll 8
                for (int k = 0; k < HID; k++) s += hb[k] * seg_w[j * HID + k];
                out[2 * Btot + b * 5 + j] = s;
            }
        }
    }
}

extern "C" void kernel_launch(void* const* d_in, const int* in_sizes, int n_in,
                              void* d_out, int out_size) {
    const float* x       = (const float*)d_in[0];
    const float* w_ih0   = (const float*)d_in[1];
    const float* w_hh0   = (const float*)d_in[2];
    const float* b_ih0   = (const float*)d_in[3];
    const float* b_hh0   = (const float*)d_in[4];
    const float* w_ih1   = (const float*)d_in[5];
    const float* w_hh1   = (const float*)d_in[6];
    const float* b_ih1   = (const float*)d_in[7];
    const float* b_hh1   = (const float*)d_in[8];
    const float* eng_w1  = (const float*)d_in[9];
    const float* eng_b1  = (const float*)d_in[10];
    const float* eng_w2  = (const float*)d_in[11];
    const float* eng_b2  = (const float*)d_in[12];
    const float* prop_w1 = (const float*)d_in[13];
    const float* prop_b1 = (const float*)d_in[14];
    const float* prop_w2 = (const float*)d_in[15];
    const float* prop_b2 = (const float*)d_in[16];
    const float* seg_w   = (const float*)d_in[17];
    const float* seg_b   = (const float*)d_in[18];
    float* out = (float*)d_out;

    int Btot = in_sizes[0] / (S_LEN * F_IN);        // 4096
    int grid = (Btot + BTILE - 1) / BTILE;          // 293

    cudaFuncSetAttribute(lstm_behavior_kernel,
                         cudaFuncAttributeMaxDynamicSharedMemorySize, SM_TOT);

    lstm_behavior_kernel<<<grid, NTH, SM_TOT>>>(
        x, w_ih0, w_hh0, b_ih0, b_hh0, w_ih1, w_hh1, b_ih1, b_hh1,
        eng_w1, eng_b1, eng_w2, eng_b2, prop_w1, prop_b1, prop_w2, prop_b2,
        seg_w, seg_b, out, Btot);
}